// round 4
// baseline (speedup 1.0000x reference)
#include <cuda_runtime.h>

#define NN 10000        // nodes
#define EE 160000       // max edges (sizing for device scratch)
#define GN 5632         // per-node g-table floats: 1536 ss + 2304 vv + 256 sv + 1536 vs
#define OFF_VV 1536
#define OFF_SV 3840
#define OFF_VS 4096

// -------- device scratch (static: allocation APIs are banned) --------
__device__ float d_Asi[NN*16];
__device__ float d_Asj[NN*16];
__device__ float d_Avi[NN*48];
__device__ float d_Avj[NN*48];
__device__ int   d_cnt[2*NN];
__device__ int   d_cur[2*NN];
__device__ int   d_off[2*(NN+1)];
__device__ int   d_list[2*EE];
__device__ float d_g[(size_t)NN*GN];        // ~225 MB, reused across passes
__device__ float d_partial[(size_t)EE*96];  // ~61 MB

__device__ __forceinline__ float fsilu(float x){ return x/(1.f+__expf(-x)); }

// -------- K0: zero accumulators + counters --------
__global__ void k_zero(){
  int i  = blockIdx.x*blockDim.x + threadIdx.x;
  int st = gridDim.x*blockDim.x;
  for (int k=i;k<NN*16;k+=st){ d_Asi[k]=0.f; d_Asj[k]=0.f; }
  for (int k=i;k<NN*48;k+=st){ d_Avi[k]=0.f; d_Avj[k]=0.f; }
  for (int k=i;k<2*NN;k+=st){ d_cnt[k]=0; d_cur[k]=0; }
}

// -------- K1: per-edge MLP + sh-mix + atomic scatter to node accumulators --------
__global__ void __launch_bounds__(128) k_mlp(
    const float* __restrict__ edge_sh, const float* __restrict__ edge_fea,
    const int* __restrict__ eidx,
    const float* __restrict__ w1, const float* __restrict__ b1,
    const float* __restrict__ w2, const float* __restrict__ b2,
    const float* __restrict__ w3, const float* __restrict__ b3, int E)
{
  extern __shared__ float sm[];
  float* sw1 = sm;          // 2048
  float* sw2 = sm+2048;     // 4096
  float* sw3 = sm+6144;     // 4096
  float* sb1 = sm+10240;    // 64
  float* sb2 = sm+10304;    // 64
  float* sb3 = sm+10368;    // 64
  float* sS  = sm+10432;    // 32*128 : transposed input features
  float* sH  = sm+14528;    // 64*128 : layer-1 activations (per-thread column)
  int t = threadIdx.x;
  for (int i=t;i<2048;i+=128) sw1[i]=w1[i];
  for (int i=t;i<4096;i+=128) sw2[i]=w2[i];
  for (int i=t;i<4096;i+=128) sw3[i]=w3[i];
  if (t<64){ sb1[t]=b1[t]; sb2[t]=b2[t]; sb3[t]=b3[t]; }
  int e0 = blockIdx.x*128;
  // stage s-features transposed: sS[i*128 + l] = edge_fea[(e0+l)*80 + i]
  for (int idx=t; idx<32*128; idx+=128){
    int l = idx & 127; int i = idx >> 7;
    int e = e0 + l;
    sS[i*128+l] = (e<E) ? edge_fea[(size_t)e*80 + i] : 0.f;
  }
  __syncthreads();
  int e = e0 + t;
  // layer 1: h = silu(s @ w1 + b1)   (accumulators j fully unrolled -> registers)
  float h[64];
  #pragma unroll
  for (int j=0;j<64;j++) h[j]=sb1[j];
  for (int i=0;i<32;i++){
    float sv = sS[i*128+t];
    #pragma unroll
    for (int j=0;j<64;j++) h[j] += sv*sw1[i*64+j];
  }
  #pragma unroll
  for (int j=0;j<64;j++){ sH[j*128+t] = fsilu(h[j]); }  // own column: no sync needed
  // layer 2: h2 = silu(h @ w2 + b2)
  float h2[64];
  #pragma unroll
  for (int j=0;j<64;j++) h2[j]=sb2[j];
  for (int i=0;i<64;i++){
    float hv = sH[i*128+t];
    #pragma unroll
    for (int j=0;j<64;j++) h2[j] += hv*sw2[i*64+j];
  }
  #pragma unroll
  for (int j=0;j<64;j++) h2[j] = fsilu(h2[j]);
  if (e < E){
    float4 sh4 = *(const float4*)(edge_sh + (size_t)e*4);
    int ni = eidx[e];
    int nj = eidx[E + e];
    // layer 3 (weight = h2 @ w3 + b3) fused with mix + scatter (all to node ni)
    for (int j=0;j<64;j++){
      float a = sb3[j];
      #pragma unroll
      for (int i=0;i<64;i++) a += h2[i]*sw3[i*64+j];
      if (j<16)       atomicAdd(&d_Asi[ni*16+j], a*sh4.x);
      else if (j<32){ int m=j-16; float* p=&d_Avi[ni*48+m*3];
                      atomicAdd(p+0,a*sh4.y); atomicAdd(p+1,a*sh4.z); atomicAdd(p+2,a*sh4.w); }
      else if (j<48)  atomicAdd(&d_Asj[ni*16+(j-32)], a*sh4.x);
      else {          int m=j-48; float* p=&d_Avj[ni*48+m*3];
                      atomicAdd(p+0,a*sh4.y); atomicAdd(p+1,a*sh4.z); atomicAdd(p+2,a*sh4.w); }
    }
    atomicAdd(&d_cnt[ni],1);
    atomicAdd(&d_cnt[NN+nj],1);
  }
}

// -------- K2: exclusive scan of both degree histograms (1 block each) --------
__global__ void k_scan(){
  int which = blockIdx.x;
  const int* cnt = d_cnt + which*NN;
  int* off = d_off + which*(NN+1);
  __shared__ int sd[1024];
  __shared__ int s_carry;
  int t = threadIdx.x;
  if (t==0) s_carry=0;
  __syncthreads();
  for (int base=0;base<NN;base+=1024){
    int x = (base+t<NN) ? cnt[base+t] : 0;
    sd[t]=x;
    __syncthreads();
    for (int d=1; d<1024; d<<=1){
      int add = (t>=d)? sd[t-d] : 0;
      __syncthreads();
      sd[t] += add;
      __syncthreads();
    }
    int incl = sd[t];
    int carry = s_carry;
    if (base+t<NN) off[base+t] = carry + incl - x;
    __syncthreads();
    if (t==1023) s_carry = carry + incl;
    __syncthreads();
  }
  if (t==0) off[NN] = s_carry;
}

// -------- K3: fill CSR edge lists for both orderings --------
__global__ void k_fill(const int* __restrict__ eidx, int E){
  int e = blockIdx.x*blockDim.x+threadIdx.x;
  if (e>=E) return;
  int ni = eidx[e];
  int nj = eidx[E+e];
  int p = atomicAdd(&d_cur[ni],1);
  d_list[d_off[ni]+p] = e;
  int q = atomicAdd(&d_cur[NN+nj],1);
  d_list[EE + d_off[(NN+1)+nj]+q] = e;
}

// -------- K4: per-node g-tables  g[n][row][o] = sum_i A[n,i(,c)] * w[o, i0+i, j] --------
// grid (44, 625), block 128, 16 nodes per block (weights register-cached across nodes)
__global__ void __launch_bounds__(128) k_g(
    const float* __restrict__ w_ss, const float* __restrict__ w_vv,
    const float* __restrict__ w_sv, const float* __restrict__ w_vs, int side)
{
  const int NT=16;
  __shared__ float sAs[NT*16];
  __shared__ float sAv[NT*48];
  int t=threadIdx.x;
  int n0=blockIdx.y*NT;
  const float* As = side ? d_Asj : d_Asi;
  const float* Av = side ? d_Avj : d_Avi;
  for (int i=t;i<NT*16;i+=128) sAs[i]=As[n0*16+i];
  for (int i=t;i<NT*48;i+=128) sAv[i]=Av[n0*48+i];
  __syncthreads();
  int elem = blockIdx.x*128 + t;          // [0, 5632), table boundaries 128-aligned
  int i0 = side ? 16 : 0;
  const float* wp; int ws; bool isAv; int aoff=0;
  if (elem < 1536){      int o=elem%48, j=elem/48;                    wp=w_ss+(size_t)(o*32+i0)*32+j; ws=32; isAv=false; }
  else if (elem < 3840){ int r=elem-1536; int o=r%48, row=r/48, j=row/3; aoff=row%3;
                         wp=w_vv+(size_t)(o*32+i0)*16+j; ws=16; isAv=true; }
  else if (elem < 4096){ int r=elem-3840; int o=r%16, j=r/16;         wp=w_sv+(size_t)(o*32+i0)*16+j; ws=16; isAv=false; }
  else {                 int r=elem-4096; int o=r%16, row=r/16, j=row/3; aoff=row%3;
                         wp=w_vs+(size_t)(o*32+i0)*32+j; ws=32; isAv=true; }
  float w[16];
  #pragma unroll
  for (int i=0;i<16;i++) w[i]=wp[(size_t)i*ws];
  #pragma unroll 4
  for (int nl=0;nl<NT;nl++){
    float acc=0.f;
    if (isAv){
      #pragma unroll
      for (int i=0;i<16;i++) acc += w[i]*sAv[nl*48+i*3+aoff];
    } else {
      #pragma unroll
      for (int i=0;i<16;i++) acc += w[i]*sAs[nl*16+i];
    }
    d_g[(size_t)(n0+nl)*GN + elem] = acc;
  }
}

// -------- K5: per-node edge contraction.  pass 0: a-side writes partials.
//             pass 1: b-side adds, finalizes (scales + silu + gates), writes output.
__global__ void __launch_bounds__(128) k_edge(
    const float* __restrict__ edge_fea, float* __restrict__ out, int pass)
{
  __shared__ float g[GN];    // transposed per-node tables: consecutive o => conflict-free
  __shared__ float sfea[80];
  __shared__ float sos[48];
  int n = blockIdx.x;
  int t = threadIdx.x;
  const int* off = d_off + pass*(NN+1);
  const int* lst = d_list + pass*EE;
  int beg = off[n], end = off[n+1];
  if (beg==end) return;                    // uniform branch
  const float* gg = d_g + (size_t)n*GN;
  for (int i=t;i<GN;i+=128) g[i]=gg[i];
  __syncthreads();
  const float inv2 = 0.7071067811865476f;
  const float c3   = 0.5773502691896258f;
  const float r512 = 0.04419417382415922f;  // 1/sqrt(512)
  const float r32  = 0.03125f;              // 1/sqrt(1024)
  for (int k=beg;k<end;k++){
    int e = lst[k];
    if (t<80) sfea[t] = edge_fea[(size_t)e*80+t];
    __syncthreads();
    float ov_tot = 0.f; int kk=0, oo=0;
    if (t<48){                              // o_s outputs
      int o=t;
      float ass=0.f, avv=0.f;
      #pragma unroll
      for (int j=0;j<32;j++) ass += sfea[j]*g[j*48+o];
      #pragma unroll
      for (int r=0;r<48;r++) avv += sfea[32+r]*g[OFF_VV+r*48+o];
      float val = inv2*(ass*r32 + c3*avv*r512);
      if (pass==0) d_partial[(size_t)e*96+o]=val;
      else         sos[o] = d_partial[(size_t)e*96+o] + val;
    } else if (t<96){                       // o_v outputs (o,c)
      kk=t-48; oo=kk/3; int c=kk-3*oo;
      float asv=0.f, avs=0.f;
      #pragma unroll
      for (int j=0;j<16;j++) asv += sfea[32+j*3+c]*g[OFF_SV+j*16+oo];
      #pragma unroll
      for (int j=0;j<32;j++) avs += sfea[j]*g[OFF_VS+(j*3+c)*16+oo];
      float val = inv2*(asv*r512 + avs*r32);
      if (pass==0) d_partial[(size_t)e*96+48+kk]=val;
      else         ov_tot = d_partial[(size_t)e*96+48+kk] + val;
    }
    __syncthreads();
    if (pass==1){
      if (t<32)                  out[(size_t)e*80+t] = fsilu(sos[t]);
      else if (t>=48 && t<96){
        float gate = 1.f/(1.f+__expf(-sos[32+oo]));
        out[(size_t)e*80+32+kk] = ov_tot*gate;
      }
    }
    __syncthreads();
  }
}

// -------- host launch --------
extern "C" void kernel_launch(void* const* d_in, const int* in_sizes, int n_in,
                              void* d_out, int out_size)
{
  const float* edge_sh  = (const float*)d_in[0];
  const float* edge_fea = (const float*)d_in[1];
  const int*   eidx     = (const int*)d_in[2];
  // d_in[3] = batch_edge (unused)
  const float* w1 = (const float*)d_in[4];
  const float* b1 = (const float*)d_in[5];
  const float* w2 = (const float*)d_in[6];
  const float* b2 = (const float*)d_in[7];
  const float* w3 = (const float*)d_in[8];
  const float* b3 = (const float*)d_in[9];
  const float* w_ss = (const float*)d_in[10];
  const float* w_vv = (const float*)d_in[11];
  const float* w_sv = (const float*)d_in[12];
  const float* w_vs = (const float*)d_in[13];
  float* out = (float*)d_out;
  int E = in_sizes[0]/4;

  const int mlp_smem = 22720*4;   // 90,880 B dynamic smem for k_mlp
  cudaFuncSetAttribute(k_mlp, cudaFuncAttributeMaxDynamicSharedMemorySize, mlp_smem);

  k_zero<<<256,256>>>();
  k_mlp<<<(E+127)/128,128,mlp_smem>>>(edge_sh,edge_fea,eidx,w1,b1,w2,b2,w3,b3,E);
  k_scan<<<2,1024>>>();
  k_fill<<<(E+255)/256,256>>>(eidx,E);
  k_g<<<dim3(44,625),128>>>(w_ss,w_vv,w_sv,w_vs,0);
  k_edge<<<NN,128>>>(edge_fea,out,0);
  k_g<<<dim3(44,625),128>>>(w_ss,w_vv,w_sv,w_vs,1);
  k_edge<<<NN,128>>>(edge_fea,out,1);
}

// round 5
// speedup vs baseline: 1.0003x; 1.0003x over previous
#include <cuda_runtime.h>

#define NN 10000        // nodes
#define EE 160000       // max edges (sizing for device scratch)
#define GN 5632         // per-node g-table floats: 1536 ss + 2304 vv + 256 sv + 1536 vs
#define OFF_VV 1536
#define OFF_SV 3840
#define OFF_VS 4096

// -------- device scratch (static: allocation APIs are banned) --------
__device__ float d_Asi[NN*16];
__device__ float d_Asj[NN*16];
__device__ float d_Avi[NN*48];
__device__ float d_Avj[NN*48];
__device__ int   d_cnt[2*NN];
__device__ int   d_cur[2*NN];
__device__ int   d_off[2*(NN+1)];
__device__ int   d_list[2*EE];
__device__ float d_g[(size_t)NN*GN];        // ~225 MB, reused across passes
__device__ float d_partial[(size_t)EE*96];  // ~61 MB

__device__ __forceinline__ float fsilu(float x){ return x/(1.f+__expf(-x)); }

// -------- K0: zero accumulators + counters --------
__global__ void k_zero(){
  int i  = blockIdx.x*blockDim.x + threadIdx.x;
  int st = gridDim.x*blockDim.x;
  for (int k=i;k<NN*16;k+=st){ d_Asi[k]=0.f; d_Asj[k]=0.f; }
  for (int k=i;k<NN*48;k+=st){ d_Avi[k]=0.f; d_Avj[k]=0.f; }
  for (int k=i;k<2*NN;k+=st){ d_cnt[k]=0; d_cur[k]=0; }
}

// -------- K1: per-edge MLP + sh-mix + atomic scatter to node accumulators --------
__global__ void __launch_bounds__(128) k_mlp(
    const float* __restrict__ edge_sh, const float* __restrict__ edge_fea,
    const int* __restrict__ eidx,
    const float* __restrict__ w1, const float* __restrict__ b1,
    const float* __restrict__ w2, const float* __restrict__ b2,
    const float* __restrict__ w3, const float* __restrict__ b3, int E)
{
  extern __shared__ float sm[];
  float* sw1 = sm;          // 2048
  float* sw2 = sm+2048;     // 4096
  float* sw3 = sm+6144;     // 4096
  float* sb1 = sm+10240;    // 64
  float* sb2 = sm+10304;    // 64
  float* sb3 = sm+10368;    // 64
  float* sS  = sm+10432;    // 32*128 : transposed input features
  float* sH  = sm+14528;    // 64*128 : layer-1 activations (per-thread column)
  int t = threadIdx.x;
  for (int i=t;i<2048;i+=128) sw1[i]=w1[i];
  for (int i=t;i<4096;i+=128) sw2[i]=w2[i];
  for (int i=t;i<4096;i+=128) sw3[i]=w3[i];
  if (t<64){ sb1[t]=b1[t]; sb2[t]=b2[t]; sb3[t]=b3[t]; }
  int e0 = blockIdx.x*128;
  // stage s-features transposed: sS[i*128 + l] = edge_fea[(e0+l)*80 + i]
  for (int idx=t; idx<32*128; idx+=128){
    int l = idx & 127; int i = idx >> 7;
    int e = e0 + l;
    sS[i*128+l] = (e<E) ? edge_fea[(size_t)e*80 + i] : 0.f;
  }
  __syncthreads();
  int e = e0 + t;
  // layer 1: h = silu(s @ w1 + b1)   (accumulators j fully unrolled -> registers)
  float h[64];
  #pragma unroll
  for (int j=0;j<64;j++) h[j]=sb1[j];
  for (int i=0;i<32;i++){
    float sv = sS[i*128+t];
    #pragma unroll
    for (int j=0;j<64;j++) h[j] += sv*sw1[i*64+j];
  }
  #pragma unroll
  for (int j=0;j<64;j++){ sH[j*128+t] = fsilu(h[j]); }  // own column: no sync needed
  // layer 2: h2 = silu(h @ w2 + b2)
  float h2[64];
  #pragma unroll
  for (int j=0;j<64;j++) h2[j]=sb2[j];
  for (int i=0;i<64;i++){
    float hv = sH[i*128+t];
    #pragma unroll
    for (int j=0;j<64;j++) h2[j] += hv*sw2[i*64+j];
  }
  #pragma unroll
  for (int j=0;j<64;j++) h2[j] = fsilu(h2[j]);
  if (e < E){
    float4 sh4 = *(const float4*)(edge_sh + (size_t)e*4);
    int ni = eidx[e];
    int nj = eidx[E + e];
    // layer 3 (weight = h2 @ w3 + b3) fused with mix + scatter (all to node ni)
    for (int j=0;j<64;j++){
      float a = sb3[j];
      #pragma unroll
      for (int i=0;i<64;i++) a += h2[i]*sw3[i*64+j];
      if (j<16)       atomicAdd(&d_Asi[ni*16+j], a*sh4.x);
      else if (j<32){ int m=j-16; float* p=&d_Avi[ni*48+m*3];
                      atomicAdd(p+0,a*sh4.y); atomicAdd(p+1,a*sh4.z); atomicAdd(p+2,a*sh4.w); }
      else if (j<48)  atomicAdd(&d_Asj[ni*16+(j-32)], a*sh4.x);
      else {          int m=j-48; float* p=&d_Avj[ni*48+m*3];
                      atomicAdd(p+0,a*sh4.y); atomicAdd(p+1,a*sh4.z); atomicAdd(p+2,a*sh4.w); }
    }
    atomicAdd(&d_cnt[ni],1);
    atomicAdd(&d_cnt[NN+nj],1);
  }
}

// -------- K2: exclusive scan of both degree histograms (1 block each) --------
__global__ void k_scan(){
  int which = blockIdx.x;
  const int* cnt = d_cnt + which*NN;
  int* off = d_off + which*(NN+1);
  __shared__ int sd[1024];
  __shared__ int s_carry;
  int t = threadIdx.x;
  if (t==0) s_carry=0;
  __syncthreads();
  for (int base=0;base<NN;base+=1024){
    int x = (base+t<NN) ? cnt[base+t] : 0;
    sd[t]=x;
    __syncthreads();
    for (int d=1; d<1024; d<<=1){
      int add = (t>=d)? sd[t-d] : 0;
      __syncthreads();
      sd[t] += add;
      __syncthreads();
    }
    int incl = sd[t];
    int carry = s_carry;
    if (base+t<NN) off[base+t] = carry + incl - x;
    __syncthreads();
    if (t==1023) s_carry = carry + incl;
    __syncthreads();
  }
  if (t==0) off[NN] = s_carry;
}

// -------- K3: fill CSR edge lists for both orderings --------
__global__ void k_fill(const int* __restrict__ eidx, int E){
  int e = blockIdx.x*blockDim.x+threadIdx.x;
  if (e>=E) return;
  int ni = eidx[e];
  int nj = eidx[E+e];
  int p = atomicAdd(&d_cur[ni],1);
  d_list[d_off[ni]+p] = e;
  int q = atomicAdd(&d_cur[NN+nj],1);
  d_list[EE + d_off[(NN+1)+nj]+q] = e;
}

// -------- K4: per-node g-tables  g[n][row][o] = sum_i A[n,i(,c)] * w[o, i0+i, j] --------
// grid (44, 625), block 128, 16 nodes per block (weights register-cached across nodes)
__global__ void __launch_bounds__(128) k_g(
    const float* __restrict__ w_ss, const float* __restrict__ w_vv,
    const float* __restrict__ w_sv, const float* __restrict__ w_vs, int side)
{
  const int NT=16;
  __shared__ float sAs[NT*16];
  __shared__ float sAv[NT*48];
  int t=threadIdx.x;
  int n0=blockIdx.y*NT;
  const float* As = side ? d_Asj : d_Asi;
  const float* Av = side ? d_Avj : d_Avi;
  for (int i=t;i<NT*16;i+=128) sAs[i]=As[n0*16+i];
  for (int i=t;i<NT*48;i+=128) sAv[i]=Av[n0*48+i];
  __syncthreads();
  int elem = blockIdx.x*128 + t;          // [0, 5632), table boundaries 128-aligned
  int i0 = side ? 16 : 0;
  const float* wp; int ws; bool isAv; int aoff=0;
  if (elem < 1536){      int o=elem%48, j=elem/48;                    wp=w_ss+(size_t)(o*32+i0)*32+j; ws=32; isAv=false; }
  else if (elem < 3840){ int r=elem-1536; int o=r%48, row=r/48, j=row/3; aoff=row%3;
                         wp=w_vv+(size_t)(o*32+i0)*16+j; ws=16; isAv=true; }
  else if (elem < 4096){ int r=elem-3840; int o=r%16, j=r/16;         wp=w_sv+(size_t)(o*32+i0)*16+j; ws=16; isAv=false; }
  else {                 int r=elem-4096; int o=r%16, row=r/16, j=row/3; aoff=row%3;
                         wp=w_vs+(size_t)(o*32+i0)*32+j; ws=32; isAv=true; }
  float w[16];
  #pragma unroll
  for (int i=0;i<16;i++) w[i]=wp[(size_t)i*ws];
  #pragma unroll 4
  for (int nl=0;nl<NT;nl++){
    float acc=0.f;
    if (isAv){
      #pragma unroll
      for (int i=0;i<16;i++) acc += w[i]*sAv[nl*48+i*3+aoff];
    } else {
      #pragma unroll
      for (int i=0;i<16;i++) acc += w[i]*sAs[nl*16+i];
    }
    d_g[(size_t)(n0+nl)*GN + elem] = acc;
  }
}

// -------- K5: per-node edge contraction.  pass 0: a-side writes partials.
//             pass 1: b-side adds, finalizes (scales + silu + gates), writes output.
__global__ void __launch_bounds__(128) k_edge(
    const float* __restrict__ edge_fea, float* __restrict__ out, int pass)
{
  __shared__ float g[GN];    // transposed per-node tables: consecutive o => conflict-free
  __shared__ float sfea[80];
  __shared__ float sos[48];
  int n = blockIdx.x;
  int t = threadIdx.x;
  const int* off = d_off + pass*(NN+1);
  const int* lst = d_list + pass*EE;
  int beg = off[n], end = off[n+1];
  if (beg==end) return;                    // uniform branch
  const float* gg = d_g + (size_t)n*GN;
  for (int i=t;i<GN;i+=128) g[i]=gg[i];
  __syncthreads();
  const float inv2 = 0.7071067811865476f;
  const float c3   = 0.5773502691896258f;
  const float r512 = 0.04419417382415922f;  // 1/sqrt(512)
  const float r32  = 0.03125f;              // 1/sqrt(1024)
  for (int k=beg;k<end;k++){
    int e = lst[k];
    if (t<80) sfea[t] = edge_fea[(size_t)e*80+t];
    __syncthreads();
    float ov_tot = 0.f; int kk=0, oo=0;
    if (t<48){                              // o_s outputs
      int o=t;
      float ass=0.f, avv=0.f;
      #pragma unroll
      for (int j=0;j<32;j++) ass += sfea[j]*g[j*48+o];
      #pragma unroll
      for (int r=0;r<48;r++) avv += sfea[32+r]*g[OFF_VV+r*48+o];
      float val = inv2*(ass*r32 + c3*avv*r512);
      if (pass==0) d_partial[(size_t)e*96+o]=val;
      else         sos[o] = d_partial[(size_t)e*96+o] + val;
    } else if (t<96){                       // o_v outputs (o,c)
      kk=t-48; oo=kk/3; int c=kk-3*oo;
      float asv=0.f, avs=0.f;
      #pragma unroll
      for (int j=0;j<16;j++) asv += sfea[32+j*3+c]*g[OFF_SV+j*16+oo];
      #pragma unroll
      for (int j=0;j<32;j++) avs += sfea[j]*g[OFF_VS+(j*3+c)*16+oo];
      float val = inv2*(asv*r512 + avs*r32);
      if (pass==0) d_partial[(size_t)e*96+48+kk]=val;
      else         ov_tot = d_partial[(size_t)e*96+48+kk] + val;
    }
    __syncthreads();
    if (pass==1){
      if (t<32)                  out[(size_t)e*80+t] = fsilu(sos[t]);
      else if (t>=48 && t<96){
        float gate = 1.f/(1.f+__expf(-sos[32+oo]));
        out[(size_t)e*80+32+kk] = ov_tot*gate;
      }
    }
    __syncthreads();
  }
}

// -------- host launch --------
extern "C" void kernel_launch(void* const* d_in, const int* in_sizes, int n_in,
                              void* d_out, int out_size)
{
  const float* edge_sh  = (const float*)d_in[0];
  const float* edge_fea = (const float*)d_in[1];
  const int*   eidx     = (const int*)d_in[2];
  // d_in[3] = batch_edge (unused)
  const float* w1 = (const float*)d_in[4];
  const float* b1 = (const float*)d_in[5];
  const float* w2 = (const float*)d_in[6];
  const float* b2 = (const float*)d_in[7];
  const float* w3 = (const float*)d_in[8];
  const float* b3 = (const float*)d_in[9];
  const float* w_ss = (const float*)d_in[10];
  const float* w_vv = (const float*)d_in[11];
  const float* w_sv = (const float*)d_in[12];
  const float* w_vs = (const float*)d_in[13];
  float* out = (float*)d_out;
  int E = in_sizes[0]/4;

  const int mlp_smem = 22720*4;   // 90,880 B dynamic smem for k_mlp
  cudaFuncSetAttribute(k_mlp, cudaFuncAttributeMaxDynamicSharedMemorySize, mlp_smem);

  k_zero<<<256,256>>>();
  k_mlp<<<(E+127)/128,128,mlp_smem>>>(edge_sh,edge_fea,eidx,w1,b1,w2,b2,w3,b3,E);
  k_scan<<<2,1024>>>();
  k_fill<<<(E+255)/256,256>>>(eidx,E);
  k_g<<<dim3(44,625),128>>>(w_ss,w_vv,w_sv,w_vs,0);
  k_edge<<<NN,128>>>(edge_fea,out,0);
  k_g<<<dim3(44,625),128>>>(w_ss,w_vv,w_sv,w_vs,1);
  k_edge<<<NN,128>>>(edge_fea,out,1);
}

// round 7
// speedup vs baseline: 1.2120x; 1.2117x over previous
#include <cuda_runtime.h>

#define NN 10000        // nodes
#define EE 160000       // max edges (sizing for device scratch)
#define GN 5632         // per-node g-table floats: 1536 ss + 2304 vv + 256 sv + 1536 vs
#define OFF_VV 1536
#define OFF_SV 3840
#define OFF_VS 4096

// -------- device scratch (static: allocation APIs are banned) --------
__device__ float d_Asi[NN*16];
__device__ float d_Asj[NN*16];
__device__ float d_Avi[NN*48];
__device__ float d_Avj[NN*48];
__device__ int   d_cnt[2*NN];
__device__ int   d_cur[2*NN];
__device__ int   d_off[2*(NN+1)];
__device__ int   d_list[2*EE];
__device__ float d_wT[2*GN*16];             // transposed weights, i-contiguous
__device__ float d_g[(size_t)NN*GN];        // ~225 MB, reused across passes
__device__ float d_partial[(size_t)EE*96];  // ~61 MB

__device__ __forceinline__ float fsilu(float x){ return x/(1.f+__expf(-x)); }

// -------- K0: zero accumulators + counters --------
__global__ void k_zero(){
  int i  = blockIdx.x*blockDim.x + threadIdx.x;
  int st = gridDim.x*blockDim.x;
  for (int k=i;k<NN*16;k+=st){ d_Asi[k]=0.f; d_Asj[k]=0.f; }
  for (int k=i;k<NN*48;k+=st){ d_Avi[k]=0.f; d_Avj[k]=0.f; }
  for (int k=i;k<2*NN;k+=st){ d_cnt[k]=0; d_cur[k]=0; }
}

// -------- K0b: build i-contiguous transposed weight table --------
// wT[side][elem][i] = w_x[o*32 + i0 + i][j]  per the elem->(table,o,j) map used by k_g.
__global__ void k_wt(const float* __restrict__ w_ss, const float* __restrict__ w_vv,
                     const float* __restrict__ w_sv, const float* __restrict__ w_vs){
  int idx = blockIdx.x*256 + threadIdx.x;
  if (idx >= 2*GN*16) return;
  int side = idx / (GN*16);
  int r0   = idx % (GN*16);
  int elem = r0 >> 4;
  int i    = (r0 & 15) + (side ? 16 : 0);
  float v;
  if (elem < 1536){      int o=elem%48, j=elem/48;              v = w_ss[(size_t)(o*32+i)*32 + j]; }
  else if (elem < 3840){ int r=elem-1536; int o=r%48, j=(r/48)/3; v = w_vv[(size_t)(o*32+i)*16 + j]; }
  else if (elem < 4096){ int r=elem-3840; int o=r%16, j=r/16;     v = w_sv[(size_t)(o*32+i)*16 + j]; }
  else {                 int r=elem-4096; int o=r%16, j=(r/16)/3; v = w_vs[(size_t)(o*32+i)*32 + j]; }
  d_wT[idx] = v;
}

// -------- K1: per-edge MLP + sh-mix + atomic scatter to node accumulators --------
__global__ void __launch_bounds__(128) k_mlp(
    const float* __restrict__ edge_sh, const float* __restrict__ edge_fea,
    const int* __restrict__ eidx,
    const float* __restrict__ w1, const float* __restrict__ b1,
    const float* __restrict__ w2, const float* __restrict__ b2,
    const float* __restrict__ w3, const float* __restrict__ b3, int E)
{
  extern __shared__ float sm[];
  float* sw1 = sm;          // 2048
  float* sw2 = sm+2048;     // 4096
  float* sw3 = sm+6144;     // 4096
  float* sb1 = sm+10240;    // 64
  float* sb2 = sm+10304;    // 64
  float* sb3 = sm+10368;    // 64
  float* sS  = sm+10432;    // 32*128 : transposed input features
  float* sH  = sm+14528;    // 64*128 : layer-1 activations (per-thread column)
  int t = threadIdx.x;
  for (int i=t;i<2048;i+=128) sw1[i]=w1[i];
  for (int i=t;i<4096;i+=128) sw2[i]=w2[i];
  for (int i=t;i<4096;i+=128) sw3[i]=w3[i];
  if (t<64){ sb1[t]=b1[t]; sb2[t]=b2[t]; sb3[t]=b3[t]; }
  int e0 = blockIdx.x*128;
  // stage s-features transposed: sS[i*128 + l] = edge_fea[(e0+l)*80 + i]
  for (int idx=t; idx<32*128; idx+=128){
    int l = idx & 127; int i = idx >> 7;
    int e = e0 + l;
    sS[i*128+l] = (e<E) ? edge_fea[(size_t)e*80 + i] : 0.f;
  }
  __syncthreads();
  int e = e0 + t;
  // layer 1: h = silu(s @ w1 + b1)
  float h[64];
  #pragma unroll
  for (int j=0;j<64;j++) h[j]=sb1[j];
  for (int i=0;i<32;i++){
    float sv = sS[i*128+t];
    #pragma unroll
    for (int j=0;j<64;j++) h[j] += sv*sw1[i*64+j];
  }
  #pragma unroll
  for (int j=0;j<64;j++){ sH[j*128+t] = fsilu(h[j]); }  // own column: no sync needed
  // layer 2: h2 = silu(h @ w2 + b2)
  float h2[64];
  #pragma unroll
  for (int j=0;j<64;j++) h2[j]=sb2[j];
  for (int i=0;i<64;i++){
    float hv = sH[i*128+t];
    #pragma unroll
    for (int j=0;j<64;j++) h2[j] += hv*sw2[i*64+j];
  }
  #pragma unroll
  for (int j=0;j<64;j++) h2[j] = fsilu(h2[j]);
  if (e < E){
    float4 sh4 = *(const float4*)(edge_sh + (size_t)e*4);
    int ni = eidx[e];
    int nj = eidx[E + e];
    // layer 3 (weight = h2 @ w3 + b3) fused with mix + scatter (all to node ni)
    for (int j=0;j<64;j++){
      float a = sb3[j];
      #pragma unroll
      for (int i=0;i<64;i++) a += h2[i]*sw3[i*64+j];
      if (j<16)       atomicAdd(&d_Asi[ni*16+j], a*sh4.x);
      else if (j<32){ int m=j-16; float* p=&d_Avi[ni*48+m*3];
                      atomicAdd(p+0,a*sh4.y); atomicAdd(p+1,a*sh4.z); atomicAdd(p+2,a*sh4.w); }
      else if (j<48)  atomicAdd(&d_Asj[ni*16+(j-32)], a*sh4.x);
      else {          int m=j-48; float* p=&d_Avj[ni*48+m*3];
                      atomicAdd(p+0,a*sh4.y); atomicAdd(p+1,a*sh4.z); atomicAdd(p+2,a*sh4.w); }
    }
    atomicAdd(&d_cnt[ni],1);
    atomicAdd(&d_cnt[NN+nj],1);
  }
}

// -------- K2: exclusive scan of both degree histograms (1 block each) --------
__global__ void k_scan(){
  int which = blockIdx.x;
  const int* cnt = d_cnt + which*NN;
  int* off = d_off + which*(NN+1);
  __shared__ int sd[1024];
  __shared__ int s_carry;
  int t = threadIdx.x;
  if (t==0) s_carry=0;
  __syncthreads();
  for (int base=0;base<NN;base+=1024){
    int x = (base+t<NN) ? cnt[base+t] : 0;
    sd[t]=x;
    __syncthreads();
    for (int d=1; d<1024; d<<=1){
      int add = (t>=d)? sd[t-d] : 0;
      __syncthreads();
      sd[t] += add;
      __syncthreads();
    }
    int incl = sd[t];
    int carry = s_carry;
    if (base+t<NN) off[base+t] = carry + incl - x;
    __syncthreads();
    if (t==1023) s_carry = carry + incl;
    __syncthreads();
  }
  if (t==0) off[NN] = s_carry;
}

// -------- K3: fill CSR edge lists for both orderings --------
__global__ void k_fill(const int* __restrict__ eidx, int E){
  int e = blockIdx.x*blockDim.x+threadIdx.x;
  if (e>=E) return;
  int ni = eidx[e];
  int nj = eidx[E+e];
  int p = atomicAdd(&d_cur[ni],1);
  d_list[d_off[ni]+p] = e;
  int q = atomicAdd(&d_cur[NN+nj],1);
  d_list[EE + d_off[(NN+1)+nj]+q] = e;
}

// -------- K4: per-node g-tables  g[n][row][o] = sum_i A[n,i(,c)] * wT[side][row][i] --------
// grid (44, 625), block 128, 16 nodes per block (weights register-cached across nodes)
__global__ void __launch_bounds__(128) k_g(int side)
{
  const int NT=16;
  __shared__ float sAs[NT*16];
  __shared__ float sAv[NT*48];
  int t=threadIdx.x;
  int n0=blockIdx.y*NT;
  const float* As = side ? d_Asj : d_Asi;
  const float* Av = side ? d_Avj : d_Avi;
  for (int i=t;i<NT*16;i+=128) sAs[i]=As[n0*16+i];
  for (int i=t;i<NT*48;i+=128) sAv[i]=Av[n0*48+i];
  __syncthreads();
  int elem = blockIdx.x*128 + t;          // [0, 5632), table boundaries 128-aligned
  bool isAv; int aoff=0;
  if (elem < 1536){      isAv=false; }
  else if (elem < 3840){ int row=(elem-1536)/48; aoff=row%3; isAv=true; }
  else if (elem < 4096){ isAv=false; }
  else {                 int row=(elem-4096)/16; aoff=row%3; isAv=true; }
  // coalesced, i-contiguous weight fetch (4x float4)
  float w[16];
  const float4* w4 = (const float4*)(d_wT + ((size_t)side*GN + elem)*16);
  {
    float4 a0=w4[0], a1=w4[1], a2=w4[2], a3=w4[3];
    w[0]=a0.x; w[1]=a0.y; w[2]=a0.z; w[3]=a0.w;
    w[4]=a1.x; w[5]=a1.y; w[6]=a1.z; w[7]=a1.w;
    w[8]=a2.x; w[9]=a2.y; w[10]=a2.z; w[11]=a2.w;
    w[12]=a3.x; w[13]=a3.y; w[14]=a3.z; w[15]=a3.w;
  }
  #pragma unroll 4
  for (int nl=0;nl<NT;nl++){
    float acc=0.f;
    if (isAv){
      #pragma unroll
      for (int i=0;i<16;i++) acc += w[i]*sAv[nl*48+i*3+aoff];
    } else {
      #pragma unroll
      for (int i=0;i<16;i++) acc += w[i]*sAs[nl*16+i];
    }
    d_g[(size_t)(n0+nl)*GN + elem] = acc;
  }
}

// -------- K5: per-node edge contraction.  pass 0: a-side writes partials.
//             pass 1: b-side adds, finalizes (scales + silu + gates), writes output.
__global__ void __launch_bounds__(128) k_edge(
    const float* __restrict__ edge_fea, float* __restrict__ out, int pass)
{
  __shared__ float g[GN];    // per-node tables, o fastest => conflict-free
  __shared__ float sfea[80];
  __shared__ float sos[48];
  int n = blockIdx.x;
  int t = threadIdx.x;
  const int* off = d_off + pass*(NN+1);
  const int* lst = d_list + pass*EE;
  int beg = off[n], end = off[n+1];
  if (beg==end) return;                    // uniform branch
  const float* gg = d_g + (size_t)n*GN;
  for (int i=t;i<GN;i+=128) g[i]=gg[i];
  __syncthreads();
  const float inv2 = 0.7071067811865476f;
  const float c3   = 0.5773502691896258f;
  const float r512 = 0.04419417382415922f;  // 1/sqrt(512)
  const float r32  = 0.03125f;              // 1/sqrt(1024)
  for (int k=beg;k<end;k++){
    int e = lst[k];
    if (t<80) sfea[t] = edge_fea[(size_t)e*80+t];
    __syncthreads();
    float ov_tot = 0.f; int kk=0, oo=0;
    if (t<48){                              // o_s outputs
      int o=t;
      float ass=0.f, avv=0.f;
      #pragma unroll
      for (int j=0;j<32;j++) ass += sfea[j]*g[j*48+o];
      #pragma unroll
      for (int r=0;r<48;r++) avv += sfea[32+r]*g[OFF_VV+r*48+o];
      float val = inv2*(ass*r32 + c3*avv*r512);
      if (pass==0) d_partial[(size_t)e*96+o]=val;
      else         sos[o] = d_partial[(size_t)e*96+o] + val;
    } else if (t<96){                       // o_v outputs (o,c)
      kk=t-48; oo=kk/3; int c=kk-3*oo;
      float asv=0.f, avs=0.f;
      #pragma unroll
      for (int j=0;j<16;j++) asv += sfea[32+j*3+c]*g[OFF_SV+j*16+oo];
      #pragma unroll
      for (int j=0;j<32;j++) avs += sfea[j]*g[OFF_VS+(j*3+c)*16+oo];
      float val = inv2*(asv*r512 + avs*r32);
      if (pass==0) d_partial[(size_t)e*96+48+kk]=val;
      else         ov_tot = d_partial[(size_t)e*96+48+kk] + val;
    }
    __syncthreads();
    if (pass==1){
      if (t<32)                  out[(size_t)e*80+t] = fsilu(sos[t]);
      else if (t>=48 && t<96){
        float gate = 1.f/(1.f+__expf(-sos[32+oo]));
        out[(size_t)e*80+32+kk] = ov_tot*gate;
      }
    }
    __syncthreads();
  }
}

// -------- host launch --------
extern "C" void kernel_launch(void* const* d_in, const int* in_sizes, int n_in,
                              void* d_out, int out_size)
{
  const float* edge_sh  = (const float*)d_in[0];
  const float* edge_fea = (const float*)d_in[1];
  const int*   eidx     = (const int*)d_in[2];
  // d_in[3] = batch_edge (unused)
  const float* w1 = (const float*)d_in[4];
  const float* b1 = (const float*)d_in[5];
  const float* w2 = (const float*)d_in[6];
  const float* b2 = (const float*)d_in[7];
  const float* w3 = (const float*)d_in[8];
  const float* b3 = (const float*)d_in[9];
  const float* w_ss = (const float*)d_in[10];
  const float* w_vv = (const float*)d_in[11];
  const float* w_sv = (const float*)d_in[12];
  const float* w_vs = (const float*)d_in[13];
  float* out = (float*)d_out;
  int E = in_sizes[0]/4;

  const int mlp_smem = 22720*4;   // 90,880 B dynamic smem for k_mlp
  cudaFuncSetAttribute(k_mlp, cudaFuncAttributeMaxDynamicSharedMemorySize, mlp_smem);

  k_zero<<<256,256>>>();
  k_wt<<<(2*GN*16+255)/256,256>>>(w_ss,w_vv,w_sv,w_vs);
  k_mlp<<<(E+127)/128,128,mlp_smem>>>(edge_sh,edge_fea,eidx,w1,b1,w2,b2,w3,b3,E);
  k_scan<<<2,1024>>>();
  k_fill<<<(E+255)/256,256>>>(eidx,E);
  k_g<<<dim3(44,625),128>>>(0);
  k_edge<<<NN,128>>>(edge_fea,out,0);
  k_g<<<dim3(44,625),128>>>(1);
  k_edge<<<NN,128>>>(edge_fea,out,1);
}

// round 8
// speedup vs baseline: 1.2123x; 1.0002x over previous
#include <cuda_runtime.h>

#define NN 10000        // nodes
#define EE 160000       // max edges (sizing for device scratch)
#define GN 5632         // per-node g-table floats: 1536 ss + 2304 vv + 256 sv + 1536 vs
#define OFF_VV 1536
#define OFF_SV 3840
#define OFF_VS 4096

// -------- device scratch (static: allocation APIs are banned) --------
__device__ float d_Asi[NN*16];
__device__ float d_Asj[NN*16];
__device__ float d_Avi[NN*48];
__device__ float d_Avj[NN*48];
__device__ int   d_cnt[2*NN];
__device__ int   d_cur[2*NN];
__device__ int   d_off[2*(NN+1)];
__device__ int   d_list[2*EE];
__device__ float d_wT[2*GN*16];             // transposed weights, i-contiguous
__device__ float d_g[(size_t)NN*GN];        // ~225 MB, reused across passes
__device__ float d_partial[(size_t)EE*96];  // ~61 MB

__device__ __forceinline__ float fsilu(float x){ return x/(1.f+__expf(-x)); }

// -------- K0: zero accumulators + counters --------
__global__ void k_zero(){
  int i  = blockIdx.x*blockDim.x + threadIdx.x;
  int st = gridDim.x*blockDim.x;
  for (int k=i;k<NN*16;k+=st){ d_Asi[k]=0.f; d_Asj[k]=0.f; }
  for (int k=i;k<NN*48;k+=st){ d_Avi[k]=0.f; d_Avj[k]=0.f; }
  for (int k=i;k<2*NN;k+=st){ d_cnt[k]=0; d_cur[k]=0; }
}

// -------- K0b: build i-contiguous transposed weight table --------
// wT[side][elem][i] = w_x[o*32 + i0 + i][j]  per the elem->(table,o,j) map used by k_g.
__global__ void k_wt(const float* __restrict__ w_ss, const float* __restrict__ w_vv,
                     const float* __restrict__ w_sv, const float* __restrict__ w_vs){
  int idx = blockIdx.x*256 + threadIdx.x;
  if (idx >= 2*GN*16) return;
  int side = idx / (GN*16);
  int r0   = idx % (GN*16);
  int elem = r0 >> 4;
  int i    = (r0 & 15) + (side ? 16 : 0);
  float v;
  if (elem < 1536){      int o=elem%48, j=elem/48;              v = w_ss[(size_t)(o*32+i)*32 + j]; }
  else if (elem < 3840){ int r=elem-1536; int o=r%48, j=(r/48)/3; v = w_vv[(size_t)(o*32+i)*16 + j]; }
  else if (elem < 4096){ int r=elem-3840; int o=r%16, j=r/16;     v = w_sv[(size_t)(o*32+i)*16 + j]; }
  else {                 int r=elem-4096; int o=r%16, j=(r/16)/3; v = w_vs[(size_t)(o*32+i)*32 + j]; }
  d_wT[idx] = v;
}

// -------- K1: per-edge MLP + sh-mix + atomic scatter to node accumulators --------
__global__ void __launch_bounds__(128) k_mlp(
    const float* __restrict__ edge_sh, const float* __restrict__ edge_fea,
    const int* __restrict__ eidx,
    const float* __restrict__ w1, const float* __restrict__ b1,
    const float* __restrict__ w2, const float* __restrict__ b2,
    const float* __restrict__ w3, const float* __restrict__ b3, int E)
{
  extern __shared__ float sm[];
  float* sw1 = sm;          // 2048
  float* sw2 = sm+2048;     // 4096
  float* sw3 = sm+6144;     // 4096
  float* sb1 = sm+10240;    // 64
  float* sb2 = sm+10304;    // 64
  float* sb3 = sm+10368;    // 64
  float* sS  = sm+10432;    // 32*128 : transposed input features
  float* sH  = sm+14528;    // 64*128 : layer-1 activations (per-thread column)
  int t = threadIdx.x;
  for (int i=t;i<2048;i+=128) sw1[i]=w1[i];
  for (int i=t;i<4096;i+=128) sw2[i]=w2[i];
  for (int i=t;i<4096;i+=128) sw3[i]=w3[i];
  if (t<64){ sb1[t]=b1[t]; sb2[t]=b2[t]; sb3[t]=b3[t]; }
  int e0 = blockIdx.x*128;
  // stage s-features transposed: sS[i*128 + l] = edge_fea[(e0+l)*80 + i]
  for (int idx=t; idx<32*128; idx+=128){
    int l = idx & 127; int i = idx >> 7;
    int e = e0 + l;
    sS[i*128+l] = (e<E) ? edge_fea[(size_t)e*80 + i] : 0.f;
  }
  __syncthreads();
  int e = e0 + t;
  // layer 1: h = silu(s @ w1 + b1)
  float h[64];
  #pragma unroll
  for (int j=0;j<64;j++) h[j]=sb1[j];
  for (int i=0;i<32;i++){
    float sv = sS[i*128+t];
    #pragma unroll
    for (int j=0;j<64;j++) h[j] += sv*sw1[i*64+j];
  }
  #pragma unroll
  for (int j=0;j<64;j++){ sH[j*128+t] = fsilu(h[j]); }  // own column: no sync needed
  // layer 2: h2 = silu(h @ w2 + b2)
  float h2[64];
  #pragma unroll
  for (int j=0;j<64;j++) h2[j]=sb2[j];
  for (int i=0;i<64;i++){
    float hv = sH[i*128+t];
    #pragma unroll
    for (int j=0;j<64;j++) h2[j] += hv*sw2[i*64+j];
  }
  #pragma unroll
  for (int j=0;j<64;j++) h2[j] = fsilu(h2[j]);
  if (e < E){
    float4 sh4 = *(const float4*)(edge_sh + (size_t)e*4);
    int ni = eidx[e];
    int nj = eidx[E + e];
    // layer 3 (weight = h2 @ w3 + b3) fused with mix + scatter (all to node ni)
    for (int j=0;j<64;j++){
      float a = sb3[j];
      #pragma unroll
      for (int i=0;i<64;i++) a += h2[i]*sw3[i*64+j];
      if (j<16)       atomicAdd(&d_Asi[ni*16+j], a*sh4.x);
      else if (j<32){ int m=j-16; float* p=&d_Avi[ni*48+m*3];
                      atomicAdd(p+0,a*sh4.y); atomicAdd(p+1,a*sh4.z); atomicAdd(p+2,a*sh4.w); }
      else if (j<48)  atomicAdd(&d_Asj[ni*16+(j-32)], a*sh4.x);
      else {          int m=j-48; float* p=&d_Avj[ni*48+m*3];
                      atomicAdd(p+0,a*sh4.y); atomicAdd(p+1,a*sh4.z); atomicAdd(p+2,a*sh4.w); }
    }
    atomicAdd(&d_cnt[ni],1);
    atomicAdd(&d_cnt[NN+nj],1);
  }
}

// -------- K2: exclusive scan of both degree histograms (1 block each) --------
__global__ void k_scan(){
  int which = blockIdx.x;
  const int* cnt = d_cnt + which*NN;
  int* off = d_off + which*(NN+1);
  __shared__ int sd[1024];
  __shared__ int s_carry;
  int t = threadIdx.x;
  if (t==0) s_carry=0;
  __syncthreads();
  for (int base=0;base<NN;base+=1024){
    int x = (base+t<NN) ? cnt[base+t] : 0;
    sd[t]=x;
    __syncthreads();
    for (int d=1; d<1024; d<<=1){
      int add = (t>=d)? sd[t-d] : 0;
      __syncthreads();
      sd[t] += add;
      __syncthreads();
    }
    int incl = sd[t];
    int carry = s_carry;
    if (base+t<NN) off[base+t] = carry + incl - x;
    __syncthreads();
    if (t==1023) s_carry = carry + incl;
    __syncthreads();
  }
  if (t==0) off[NN] = s_carry;
}

// -------- K3: fill CSR edge lists for both orderings --------
__global__ void k_fill(const int* __restrict__ eidx, int E){
  int e = blockIdx.x*blockDim.x+threadIdx.x;
  if (e>=E) return;
  int ni = eidx[e];
  int nj = eidx[E+e];
  int p = atomicAdd(&d_cur[ni],1);
  d_list[d_off[ni]+p] = e;
  int q = atomicAdd(&d_cur[NN+nj],1);
  d_list[EE + d_off[(NN+1)+nj]+q] = e;
}

// -------- K4: per-node g-tables  g[n][row][o] = sum_i A[n,i(,c)] * wT[side][row][i] --------
// grid (44, 625), block 128, 16 nodes per block (weights register-cached across nodes)
__global__ void __launch_bounds__(128) k_g(int side)
{
  const int NT=16;
  __shared__ float sAs[NT*16];
  __shared__ float sAv[NT*48];
  int t=threadIdx.x;
  int n0=blockIdx.y*NT;
  const float* As = side ? d_Asj : d_Asi;
  const float* Av = side ? d_Avj : d_Avi;
  for (int i=t;i<NT*16;i+=128) sAs[i]=As[n0*16+i];
  for (int i=t;i<NT*48;i+=128) sAv[i]=Av[n0*48+i];
  __syncthreads();
  int elem = blockIdx.x*128 + t;          // [0, 5632), table boundaries 128-aligned
  bool isAv; int aoff=0;
  if (elem < 1536){      isAv=false; }
  else if (elem < 3840){ int row=(elem-1536)/48; aoff=row%3; isAv=true; }
  else if (elem < 4096){ isAv=false; }
  else {                 int row=(elem-4096)/16; aoff=row%3; isAv=true; }
  // coalesced, i-contiguous weight fetch (4x float4)
  float w[16];
  const float4* w4 = (const float4*)(d_wT + ((size_t)side*GN + elem)*16);
  {
    float4 a0=w4[0], a1=w4[1], a2=w4[2], a3=w4[3];
    w[0]=a0.x; w[1]=a0.y; w[2]=a0.z; w[3]=a0.w;
    w[4]=a1.x; w[5]=a1.y; w[6]=a1.z; w[7]=a1.w;
    w[8]=a2.x; w[9]=a2.y; w[10]=a2.z; w[11]=a2.w;
    w[12]=a3.x; w[13]=a3.y; w[14]=a3.z; w[15]=a3.w;
  }
  #pragma unroll 4
  for (int nl=0;nl<NT;nl++){
    float acc=0.f;
    if (isAv){
      #pragma unroll
      for (int i=0;i<16;i++) acc += w[i]*sAv[nl*48+i*3+aoff];
    } else {
      #pragma unroll
      for (int i=0;i<16;i++) acc += w[i]*sAs[nl*16+i];
    }
    d_g[(size_t)(n0+nl)*GN + elem] = acc;
  }
}

// -------- K5: per-node edge contraction.  pass 0: a-side writes partials.
//             pass 1: b-side adds, finalizes (scales + silu + gates), writes output.
__global__ void __launch_bounds__(128) k_edge(
    const float* __restrict__ edge_fea, float* __restrict__ out, int pass)
{
  __shared__ float g[GN];    // per-node tables, o fastest => conflict-free
  __shared__ float sfea[80];
  __shared__ float sos[48];
  int n = blockIdx.x;
  int t = threadIdx.x;
  const int* off = d_off + pass*(NN+1);
  const int* lst = d_list + pass*EE;
  int beg = off[n], end = off[n+1];
  if (beg==end) return;                    // uniform branch
  const float* gg = d_g + (size_t)n*GN;
  for (int i=t;i<GN;i+=128) g[i]=gg[i];
  __syncthreads();
  const float inv2 = 0.7071067811865476f;
  const float c3   = 0.5773502691896258f;
  const float r512 = 0.04419417382415922f;  // 1/sqrt(512)
  const float r32  = 0.03125f;              // 1/sqrt(1024)
  for (int k=beg;k<end;k++){
    int e = lst[k];
    if (t<80) sfea[t] = edge_fea[(size_t)e*80+t];
    __syncthreads();
    float ov_tot = 0.f; int kk=0, oo=0;
    if (t<48){                              // o_s outputs
      int o=t;
      float ass=0.f, avv=0.f;
      #pragma unroll
      for (int j=0;j<32;j++) ass += sfea[j]*g[j*48+o];
      #pragma unroll
      for (int r=0;r<48;r++) avv += sfea[32+r]*g[OFF_VV+r*48+o];
      float val = inv2*(ass*r32 + c3*avv*r512);
      if (pass==0) d_partial[(size_t)e*96+o]=val;
      else         sos[o] = d_partial[(size_t)e*96+o] + val;
    } else if (t<96){                       // o_v outputs (o,c)
      kk=t-48; oo=kk/3; int c=kk-3*oo;
      float asv=0.f, avs=0.f;
      #pragma unroll
      for (int j=0;j<16;j++) asv += sfea[32+j*3+c]*g[OFF_SV+j*16+oo];
      #pragma unroll
      for (int j=0;j<32;j++) avs += sfea[j]*g[OFF_VS+(j*3+c)*16+oo];
      float val = inv2*(asv*r512 + avs*r32);
      if (pass==0) d_partial[(size_t)e*96+48+kk]=val;
      else         ov_tot = d_partial[(size_t)e*96+48+kk] + val;
    }
    __syncthreads();
    if (pass==1){
      if (t<32)                  out[(size_t)e*80+t] = fsilu(sos[t]);
      else if (t>=48 && t<96){
        float gate = 1.f/(1.f+__expf(-sos[32+oo]));
        out[(size_t)e*80+32+kk] = ov_tot*gate;
      }
    }
    __syncthreads();
  }
}

// -------- host launch --------
extern "C" void kernel_launch(void* const* d_in, const int* in_sizes, int n_in,
                              void* d_out, int out_size)
{
  const float* edge_sh  = (const float*)d_in[0];
  const float* edge_fea = (const float*)d_in[1];
  const int*   eidx     = (const int*)d_in[2];
  // d_in[3] = batch_edge (unused)
  const float* w1 = (const float*)d_in[4];
  const float* b1 = (const float*)d_in[5];
  const float* w2 = (const float*)d_in[6];
  const float* b2 = (const float*)d_in[7];
  const float* w3 = (const float*)d_in[8];
  const float* b3 = (const float*)d_in[9];
  const float* w_ss = (const float*)d_in[10];
  const float* w_vv = (const float*)d_in[11];
  const float* w_sv = (const float*)d_in[12];
  const float* w_vs = (const float*)d_in[13];
  float* out = (float*)d_out;
  int E = in_sizes[0]/4;

  const int mlp_smem = 22720*4;   // 90,880 B dynamic smem for k_mlp
  cudaFuncSetAttribute(k_mlp, cudaFuncAttributeMaxDynamicSharedMemorySize, mlp_smem);

  k_zero<<<256,256>>>();
  k_wt<<<(2*GN*16+255)/256,256>>>(w_ss,w_vv,w_sv,w_vs);
  k_mlp<<<(E+127)/128,128,mlp_smem>>>(edge_sh,edge_fea,eidx,w1,b1,w2,b2,w3,b3,E);
  k_scan<<<2,1024>>>();
  k_fill<<<(E+255)/256,256>>>(eidx,E);
  k_g<<<dim3(44,625),128>>>(0);
  k_edge<<<NN,128>>>(edge_fea,out,0);
  k_g<<<dim3(44,625),128>>>(1);
  k_edge<<<NN,128>>>(edge_fea,out,1);
}

// round 9
// speedup vs baseline: 1.2136x; 1.0011x over previous
#include <cuda_runtime.h>

#define NN 10000        // nodes
#define EE 160000       // max edges (sizing for device scratch)
#define GN 5632         // per-node g-table floats: 1536 ss + 2304 vv + 256 sv + 1536 vs
#define OFF_VV 1536
#define OFF_SV 3840
#define OFF_VS 4096

// -------- device scratch (static: allocation APIs are banned) --------
__device__ float d_Asi[NN*16];
__device__ float d_Asj[NN*16];
__device__ float d_Avi[NN*48];
__device__ float d_Avj[NN*48];
__device__ int   d_cnt[2*NN];
__device__ int   d_cur[2*NN];
__device__ int   d_off[2*(NN+1)];
__device__ int   d_list[2*EE];
__device__ float d_wT[2*GN*16];             // transposed weights, i-contiguous
__device__ float d_g[(size_t)NN*GN];        // ~225 MB, reused across passes
__device__ float d_partial[(size_t)EE*96];  // ~61 MB

__device__ __forceinline__ float fsilu(float x){ return x/(1.f+__expf(-x)); }

// -------- K0: zero accumulators + counters --------
__global__ void k_zero(){
  int i  = blockIdx.x*blockDim.x + threadIdx.x;
  int st = gridDim.x*blockDim.x;
  for (int k=i;k<NN*16;k+=st){ d_Asi[k]=0.f; d_Asj[k]=0.f; }
  for (int k=i;k<NN*48;k+=st){ d_Avi[k]=0.f; d_Avj[k]=0.f; }
  for (int k=i;k<2*NN;k+=st){ d_cnt[k]=0; d_cur[k]=0; }
}

// -------- K0b: build i-contiguous transposed weight table --------
// wT[side][elem][i] = w_x[o*32 + i0 + i][j]  per the elem->(table,o,j) map used by k_g.
__global__ void k_wt(const float* __restrict__ w_ss, const float* __restrict__ w_vv,
                     const float* __restrict__ w_sv, const float* __restrict__ w_vs){
  int idx = blockIdx.x*256 + threadIdx.x;
  if (idx >= 2*GN*16) return;
  int side = idx / (GN*16);
  int r0   = idx % (GN*16);
  int elem = r0 >> 4;
  int i    = (r0 & 15) + (side ? 16 : 0);
  float v;
  if (elem < 1536){      int o=elem%48, j=elem/48;              v = w_ss[(size_t)(o*32+i)*32 + j]; }
  else if (elem < 3840){ int r=elem-1536; int o=r%48, j=(r/48)/3; v = w_vv[(size_t)(o*32+i)*16 + j]; }
  else if (elem < 4096){ int r=elem-3840; int o=r%16, j=r/16;     v = w_sv[(size_t)(o*32+i)*16 + j]; }
  else {                 int r=elem-4096; int o=r%16, j=(r/16)/3; v = w_vs[(size_t)(o*32+i)*32 + j]; }
  d_wT[idx] = v;
}

// -------- K1: per-edge MLP + sh-mix + atomic scatter to node accumulators --------
__global__ void __launch_bounds__(128) k_mlp(
    const float* __restrict__ edge_sh, const float* __restrict__ edge_fea,
    const int* __restrict__ eidx,
    const float* __restrict__ w1, const float* __restrict__ b1,
    const float* __restrict__ w2, const float* __restrict__ b2,
    const float* __restrict__ w3, const float* __restrict__ b3, int E)
{
  extern __shared__ float sm[];
  float* sw1 = sm;          // 2048
  float* sw2 = sm+2048;     // 4096
  float* sw3 = sm+6144;     // 4096
  float* sb1 = sm+10240;    // 64
  float* sb2 = sm+10304;    // 64
  float* sb3 = sm+10368;    // 64
  float* sS  = sm+10432;    // 32*128 : transposed input features
  float* sH  = sm+14528;    // 64*128 : layer-1 activations (per-thread column)
  int t = threadIdx.x;
  for (int i=t;i<2048;i+=128) sw1[i]=w1[i];
  for (int i=t;i<4096;i+=128) sw2[i]=w2[i];
  for (int i=t;i<4096;i+=128) sw3[i]=w3[i];
  if (t<64){ sb1[t]=b1[t]; sb2[t]=b2[t]; sb3[t]=b3[t]; }
  int e0 = blockIdx.x*128;
  // stage s-features transposed: sS[i*128 + l] = edge_fea[(e0+l)*80 + i]
  for (int idx=t; idx<32*128; idx+=128){
    int l = idx & 127; int i = idx >> 7;
    int e = e0 + l;
    sS[i*128+l] = (e<E) ? edge_fea[(size_t)e*80 + i] : 0.f;
  }
  __syncthreads();
  int e = e0 + t;
  // layer 1: h = silu(s @ w1 + b1)
  float h[64];
  #pragma unroll
  for (int j=0;j<64;j++) h[j]=sb1[j];
  for (int i=0;i<32;i++){
    float sv = sS[i*128+t];
    #pragma unroll
    for (int j=0;j<64;j++) h[j] += sv*sw1[i*64+j];
  }
  #pragma unroll
  for (int j=0;j<64;j++){ sH[j*128+t] = fsilu(h[j]); }  // own column: no sync needed
  // layer 2: h2 = silu(h @ w2 + b2)
  float h2[64];
  #pragma unroll
  for (int j=0;j<64;j++) h2[j]=sb2[j];
  for (int i=0;i<64;i++){
    float hv = sH[i*128+t];
    #pragma unroll
    for (int j=0;j<64;j++) h2[j] += hv*sw2[i*64+j];
  }
  #pragma unroll
  for (int j=0;j<64;j++) h2[j] = fsilu(h2[j]);
  if (e < E){
    float4 sh4 = *(const float4*)(edge_sh + (size_t)e*4);
    int ni = eidx[e];
    int nj = eidx[E + e];
    // layer 3 (weight = h2 @ w3 + b3) fused with mix + scatter (all to node ni)
    for (int j=0;j<64;j++){
      float a = sb3[j];
      #pragma unroll
      for (int i=0;i<64;i++) a += h2[i]*sw3[i*64+j];
      if (j<16)       atomicAdd(&d_Asi[ni*16+j], a*sh4.x);
      else if (j<32){ int m=j-16; float* p=&d_Avi[ni*48+m*3];
                      atomicAdd(p+0,a*sh4.y); atomicAdd(p+1,a*sh4.z); atomicAdd(p+2,a*sh4.w); }
      else if (j<48)  atomicAdd(&d_Asj[ni*16+(j-32)], a*sh4.x);
      else {          int m=j-48; float* p=&d_Avj[ni*48+m*3];
                      atomicAdd(p+0,a*sh4.y); atomicAdd(p+1,a*sh4.z); atomicAdd(p+2,a*sh4.w); }
    }
    atomicAdd(&d_cnt[ni],1);
    atomicAdd(&d_cnt[NN+nj],1);
  }
}

// -------- K2: exclusive scan of both degree histograms (1 block each) --------
__global__ void k_scan(){
  int which = blockIdx.x;
  const int* cnt = d_cnt + which*NN;
  int* off = d_off + which*(NN+1);
  __shared__ int sd[1024];
  __shared__ int s_carry;
  int t = threadIdx.x;
  if (t==0) s_carry=0;
  __syncthreads();
  for (int base=0;base<NN;base+=1024){
    int x = (base+t<NN) ? cnt[base+t] : 0;
    sd[t]=x;
    __syncthreads();
    for (int d=1; d<1024; d<<=1){
      int add = (t>=d)? sd[t-d] : 0;
      __syncthreads();
      sd[t] += add;
      __syncthreads();
    }
    int incl = sd[t];
    int carry = s_carry;
    if (base+t<NN) off[base+t] = carry + incl - x;
    __syncthreads();
    if (t==1023) s_carry = carry + incl;
    __syncthreads();
  }
  if (t==0) off[NN] = s_carry;
}

// -------- K3: fill CSR edge lists for both orderings --------
__global__ void k_fill(const int* __restrict__ eidx, int E){
  int e = blockIdx.x*blockDim.x+threadIdx.x;
  if (e>=E) return;
  int ni = eidx[e];
  int nj = eidx[E+e];
  int p = atomicAdd(&d_cur[ni],1);
  d_list[d_off[ni]+p] = e;
  int q = atomicAdd(&d_cur[NN+nj],1);
  d_list[EE + d_off[(NN+1)+nj]+q] = e;
}

// -------- K4: per-node g-tables  g[n][row][o] = sum_i A[n,i(,c)] * wT[side][row][i] --------
// grid (44, 625), block 128, 16 nodes per block (weights register-cached across nodes)
__global__ void __launch_bounds__(128) k_g(int side)
{
  const int NT=16;
  __shared__ float sAs[NT*16];
  __shared__ float sAv[NT*48];
  int t=threadIdx.x;
  int n0=blockIdx.y*NT;
  const float* As = side ? d_Asj : d_Asi;
  const float* Av = side ? d_Avj : d_Avi;
  for (int i=t;i<NT*16;i+=128) sAs[i]=As[n0*16+i];
  for (int i=t;i<NT*48;i+=128) sAv[i]=Av[n0*48+i];
  __syncthreads();
  int elem = blockIdx.x*128 + t;          // [0, 5632), table boundaries 128-aligned
  bool isAv; int aoff=0;
  if (elem < 1536){      isAv=false; }
  else if (elem < 3840){ int row=(elem-1536)/48; aoff=row%3; isAv=true; }
  else if (elem < 4096){ isAv=false; }
  else {                 int row=(elem-4096)/16; aoff=row%3; isAv=true; }
  // coalesced, i-contiguous weight fetch (4x float4)
  float w[16];
  const float4* w4 = (const float4*)(d_wT + ((size_t)side*GN + elem)*16);
  {
    float4 a0=w4[0], a1=w4[1], a2=w4[2], a3=w4[3];
    w[0]=a0.x; w[1]=a0.y; w[2]=a0.z; w[3]=a0.w;
    w[4]=a1.x; w[5]=a1.y; w[6]=a1.z; w[7]=a1.w;
    w[8]=a2.x; w[9]=a2.y; w[10]=a2.z; w[11]=a2.w;
    w[12]=a3.x; w[13]=a3.y; w[14]=a3.z; w[15]=a3.w;
  }
  #pragma unroll 4
  for (int nl=0;nl<NT;nl++){
    float acc=0.f;
    if (isAv){
      #pragma unroll
      for (int i=0;i<16;i++) acc += w[i]*sAv[nl*48+i*3+aoff];
    } else {
      #pragma unroll
      for (int i=0;i<16;i++) acc += w[i]*sAs[nl*16+i];
    }
    d_g[(size_t)(n0+nl)*GN + elem] = acc;
  }
}

// -------- K5: per-node edge contraction.  pass 0: a-side writes partials.
//             pass 1: b-side adds, finalizes (scales + silu + gates), writes output.
__global__ void __launch_bounds__(128) k_edge(
    const float* __restrict__ edge_fea, float* __restrict__ out, int pass)
{
  __shared__ float g[GN];    // per-node tables, o fastest => conflict-free
  __shared__ float sfea[80];
  __shared__ float sos[48];
  int n = blockIdx.x;
  int t = threadIdx.x;
  const int* off = d_off + pass*(NN+1);
  const int* lst = d_list + pass*EE;
  int beg = off[n], end = off[n+1];
  if (beg==end) return;                    // uniform branch
  const float* gg = d_g + (size_t)n*GN;
  for (int i=t;i<GN;i+=128) g[i]=gg[i];
  __syncthreads();
  const float inv2 = 0.7071067811865476f;
  const float c3   = 0.5773502691896258f;
  const float r512 = 0.04419417382415922f;  // 1/sqrt(512)
  const float r32  = 0.03125f;              // 1/sqrt(1024)
  for (int k=beg;k<end;k++){
    int e = lst[k];
    if (t<80) sfea[t] = edge_fea[(size_t)e*80+t];
    __syncthreads();
    float ov_tot = 0.f; int kk=0, oo=0;
    if (t<48){                              // o_s outputs
      int o=t;
      float ass=0.f, avv=0.f;
      #pragma unroll
      for (int j=0;j<32;j++) ass += sfea[j]*g[j*48+o];
      #pragma unroll
      for (int r=0;r<48;r++) avv += sfea[32+r]*g[OFF_VV+r*48+o];
      float val = inv2*(ass*r32 + c3*avv*r512);
      if (pass==0) d_partial[(size_t)e*96+o]=val;
      else         sos[o] = d_partial[(size_t)e*96+o] + val;
    } else if (t<96){                       // o_v outputs (o,c)
      kk=t-48; oo=kk/3; int c=kk-3*oo;
      float asv=0.f, avs=0.f;
      #pragma unroll
      for (int j=0;j<16;j++) asv += sfea[32+j*3+c]*g[OFF_SV+j*16+oo];
      #pragma unroll
      for (int j=0;j<32;j++) avs += sfea[j]*g[OFF_VS+(j*3+c)*16+oo];
      float val = inv2*(asv*r512 + avs*r32);
      if (pass==0) d_partial[(size_t)e*96+48+kk]=val;
      else         ov_tot = d_partial[(size_t)e*96+48+kk] + val;
    }
    __syncthreads();
    if (pass==1){
      if (t<32)                  out[(size_t)e*80+t] = fsilu(sos[t]);
      else if (t>=48 && t<96){
        float gate = 1.f/(1.f+__expf(-sos[32+oo]));
        out[(size_t)e*80+32+kk] = ov_tot*gate;
      }
    }
    __syncthreads();
  }
}

// -------- host launch --------
extern "C" void kernel_launch(void* const* d_in, const int* in_sizes, int n_in,
                              void* d_out, int out_size)
{
  const float* edge_sh  = (const float*)d_in[0];
  const float* edge_fea = (const float*)d_in[1];
  const int*   eidx     = (const int*)d_in[2];
  // d_in[3] = batch_edge (unused)
  const float* w1 = (const float*)d_in[4];
  const float* b1 = (const float*)d_in[5];
  const float* w2 = (const float*)d_in[6];
  const float* b2 = (const float*)d_in[7];
  const float* w3 = (const float*)d_in[8];
  const float* b3 = (const float*)d_in[9];
  const float* w_ss = (const float*)d_in[10];
  const float* w_vv = (const float*)d_in[11];
  const float* w_sv = (const float*)d_in[12];
  const float* w_vs = (const float*)d_in[13];
  float* out = (float*)d_out;
  int E = in_sizes[0]/4;

  const int mlp_smem = 22720*4;   // 90,880 B dynamic smem for k_mlp
  cudaFuncSetAttribute(k_mlp, cudaFuncAttributeMaxDynamicSharedMemorySize, mlp_smem);

  k_zero<<<256,256>>>();
  k_wt<<<(2*GN*16+255)/256,256>>>(w_ss,w_vv,w_sv,w_vs);
  k_mlp<<<(E+127)/128,128,mlp_smem>>>(edge_sh,edge_fea,eidx,w1,b1,w2,b2,w3,b3,E);
  k_scan<<<2,1024>>>();
  k_fill<<<(E+255)/256,256>>>(eidx,E);
  k_g<<<dim3(44,625),128>>>(0);
  k_edge<<<NN,128>>>(edge_fea,out,0);
  k_g<<<dim3(44,625),128>>>(1);
  k_edge<<<NN,128>>>(edge_fea,out,1);
}